// round 15
// baseline (speedup 1.0000x reference)
#include <cuda_runtime.h>
#include <cuda_fp16.h>
#include <cstddef>
#include <cstdint>

// ---------------------------------------------------------------------------
// Problem constants
// ---------------------------------------------------------------------------
#define BATCH   8
#define CH      64
#define NPTS    32768
#define RES     32
#define RCUBE   32768
#define GRID_ELEMS (BATCH*CH*RCUBE)
#define LEAK    0.1f
#define NORM_EPS 1e-4f

#define OFF_FUSED   0
#define OFF_COORDS  (BATCH*CH*NPTS)
#define OFF_VF      (OFF_COORDS + BATCH*3*NPTS)

// ---------------------------------------------------------------------------
// Scratch
// ---------------------------------------------------------------------------
__device__ float g_sums[GRID_ELEMS];     // CHANNEL-LAST: [b][vox][64c]
__device__ float g_cnt [BATCH*RCUBE];
__device__ float g_tmp [GRID_ELEMS];     // conv2 raw out, [b][c][vox] fp32
__device__ float g_p   [GRID_ELEMS];
__device__ float g_nc  [BATCH*3*NPTS];
__device__ float g_mean[BATCH*3];
__device__ float g_denom[BATCH];
__device__ float g_st1s[BATCH*CH];
__device__ float g_st1q[BATCH*CH];
__device__ float g_st2s[BATCH*CH];
__device__ float g_st2q[BATCH*CH];
__device__ float g_psts[BATCH*CH];
__device__ float g_pstq[BATCH*CH];

// fp16 staging
__device__ __align__(16) __half g_ahi[GRID_ELEMS];     // conv input, [b][vox][c]
__device__ __align__(16) __half g_tmp16[GRID_ELEMS];   // conv1 raw out, [b][vox][c]
__device__ __align__(16) __half g_w1h[27*64*64];
__device__ __align__(16) __half g_w2h[27*64*64];
__device__ __align__(16) __half g_vfth[GRID_ELEMS];    // voxel feats, [b][vox][c]

// ---------------------------------------------------------------------------
// mma.m16n8k16 fp16 -> fp32
// ---------------------------------------------------------------------------
__device__ __forceinline__ void mma_fp16(float* d, const uint32_t* a,
                                         uint32_t b0, uint32_t b1) {
    asm volatile(
        "mma.sync.aligned.m16n8k16.row.col.f32.f16.f16.f32 "
        "{%0,%1,%2,%3}, {%4,%5,%6,%7}, {%8,%9}, {%0,%1,%2,%3};"
        : "+f"(d[0]), "+f"(d[1]), "+f"(d[2]), "+f"(d[3])
        : "r"(a[0]), "r"(a[1]), "r"(a[2]), "r"(a[3]), "r"(b0), "r"(b1));
}

__device__ __forceinline__ void red_add_v4(float* p, float a, float b, float c, float d) {
    asm volatile("red.global.add.v4.f32 [%0], {%1,%2,%3,%4};"
                 :: "l"(p), "f"(a), "f"(b), "f"(c), "f"(d) : "memory");
}

__device__ __forceinline__ uint32_t smem_u32(const void* p) {
    uint32_t a;
    asm("{ .reg .u64 t; cvta.to.shared.u64 t, %1; cvt.u32.u64 %0, t; }"
        : "=r"(a) : "l"(p));
    return a;
}

#define CP_ASYNC16(dst, src, sz) \
    asm volatile("cp.async.cg.shared.global [%0], [%1], 16, %2;" \
                 :: "r"(dst), "l"(src), "r"(sz) : "memory")
#define CP_COMMIT() asm volatile("cp.async.commit_group;" ::: "memory")
#define CP_WAIT0()  asm volatile("cp.async.wait_group 0;" ::: "memory")

// ---------------------------------------------------------------------------
// 0. zero per-(b,c) stats (bulk arrays zeroed via cudaMemsetAsync)
// ---------------------------------------------------------------------------
__global__ void zero_stats_kernel() {
    int t = blockIdx.x*blockDim.x + threadIdx.x;
    if (t < BATCH*CH) {
        g_st1s[t] = 0.f; g_st1q[t] = 0.f;
        g_st2s[t] = 0.f; g_st2q[t] = 0.f;
        g_psts[t] = 0.f; g_pstq[t] = 0.f;
    }
}

// ---------------------------------------------------------------------------
// 1. per-batch coordinate mean + max point norm (merged)
// ---------------------------------------------------------------------------
__global__ void meannorm_kernel(const float* __restrict__ coords) {
    int b = blockIdx.x, tid = threadIdx.x;
    const float* cb = coords + (size_t)b*3*NPTS;
    float s0 = 0.f, s1 = 0.f, s2 = 0.f;
    for (int n = tid; n < NPTS; n += 256) {
        s0 += cb[n]; s1 += cb[NPTS + n]; s2 += cb[2*NPTS + n];
    }
    for (int o = 16; o; o >>= 1) {
        s0 += __shfl_xor_sync(0xffffffffu, s0, o);
        s1 += __shfl_xor_sync(0xffffffffu, s1, o);
        s2 += __shfl_xor_sync(0xffffffffu, s2, o);
    }
    __shared__ float sh[3][8];
    __shared__ float sm0, sm1, sm2;
    int w = tid >> 5;
    if ((tid & 31) == 0) { sh[0][w] = s0; sh[1][w] = s1; sh[2][w] = s2; }
    __syncthreads();
    if (tid == 0) {
        float t0 = 0.f, t1 = 0.f, t2 = 0.f;
        for (int i = 0; i < 8; i++) { t0 += sh[0][i]; t1 += sh[1][i]; t2 += sh[2][i]; }
        sm0 = t0 / (float)NPTS;
        sm1 = t1 / (float)NPTS;
        sm2 = t2 / (float)NPTS;
        g_mean[b*3+0] = sm0;
        g_mean[b*3+1] = sm1;
        g_mean[b*3+2] = sm2;
    }
    __syncthreads();
    float m0 = sm0, m1 = sm1, m2 = sm2;
    float mx = 0.f;
    for (int n = tid; n < NPTS; n += 256) {
        float dx = cb[n] - m0, dy = cb[NPTS+n] - m1, dz = cb[2*NPTS+n] - m2;
        float sq = dx*dx + dy*dy + dz*dz;
        mx = fmaxf(mx, sq);
    }
    for (int o = 16; o; o >>= 1) mx = fmaxf(mx, __shfl_xor_sync(0xffffffffu, mx, o));
    __shared__ float shm[8];
    if ((tid & 31) == 0) shm[w] = mx;
    __syncthreads();
    if (tid == 0) {
        float t = 0.f;
        for (int i = 0; i < 8; i++) t = fmaxf(t, shm[i]);
        g_denom[b] = 2.0f * sqrtf(t);
    }
}

// ---------------------------------------------------------------------------
// 3. norm_coords + scatter-add (channel-last sums, v4 vector reductions)
// ---------------------------------------------------------------------------
__global__ void voxscatter_kernel(const float* __restrict__ coords,
                                  const float* __restrict__ features) {
    int t = blockIdx.x*blockDim.x + threadIdx.x;
    int b = t >> 15, n = t & (NPTS-1);
    float den = g_denom[b];
    int vi[3];
#pragma unroll
    for (int d = 0; d < 3; d++) {
        float c = coords[((size_t)b*3 + d)*NPTS + n];
        float v = (c - g_mean[b*3+d]) / den + 0.5f;
        v *= (float)RES;
        v = fminf(fmaxf(v, 0.f), (float)(RES-1));
        g_nc[((size_t)b*3 + d)*NPTS + n] = v;
        vi[d] = (int)rintf(v);
    }
    int vox = vi[0]*RES*RES + vi[1]*RES + vi[2];
    atomicAdd(&g_cnt[b*RCUBE + vox], 1.f);
    size_t fb = (size_t)b*CH*NPTS + n;
    size_t sb = ((size_t)b*RCUBE + vox)*64;
#pragma unroll 4
    for (int c = 0; c < CH; c += 4) {
        float v0 = features[fb + (size_t)(c+0)*NPTS];
        float v1 = features[fb + (size_t)(c+1)*NPTS];
        float v2 = features[fb + (size_t)(c+2)*NPTS];
        float v3 = features[fb + (size_t)(c+3)*NPTS];
        red_add_v4(&g_sums[sb + c], v0, v1, v2, v3);
    }
}

// ---------------------------------------------------------------------------
// 4. FUSED: average + fp16 convert (conv1 input prep), pure streaming
// ---------------------------------------------------------------------------
__global__ void avg_aprep_kernel() {
    int i = blockIdx.x*256 + threadIdx.x;
    int bv = i >> 4;
    float cv = fmaxf(g_cnt[bv], 1.f);
    float4 v = ((const float4*)g_sums)[i];
    ((__half2*)g_ahi)[i*2    ] = __halves2half2(__float2half_rn(v.x / cv),
                                                __float2half_rn(v.y / cv));
    ((__half2*)g_ahi)[i*2 + 1] = __halves2half2(__float2half_rn(v.z / cv),
                                                __float2half_rn(v.w / cv));
}

// ---------------------------------------------------------------------------
// 5. instnorm-apply(+leaky), fp16 channel-last -> fp16 channel-last (streaming)
//    grid.y = b; per-block stats staged in smem.
// ---------------------------------------------------------------------------
__global__ void in_aprep_kernel(const float* __restrict__ ss, const float* __restrict__ sq) {
    __shared__ float sm[64], sr[64];
    int b = blockIdx.y;
    int tid = threadIdx.x;
    if (tid < 64) {
        float m   = ss[b*CH + tid] / (float)RCUBE;
        float var = fmaxf(sq[b*CH + tid] / (float)RCUBE - m*m, 0.f);
        sm[tid] = m;
        sr[tid] = rsqrtf(var + NORM_EPS);
    }
    __syncthreads();
    // each thread: one half2 (2 channels) per iteration
    int i = blockIdx.x*256 + tid;                       // half2 index within batch b
    const __half2* src = (const __half2*)(g_tmp16 + (size_t)b*RCUBE*CH);
    __half2* dst = (__half2*)(g_ahi + (size_t)b*RCUBE*CH);
    int c2 = (i & 31);                                  // half2 lane within 64-ch row
    float2 x = __half22float2(src[i]);
    float v0 = (x.x - sm[c2*2])   * sr[c2*2];
    float v1 = (x.y - sm[c2*2+1]) * sr[c2*2+1];
    v0 = (v0 >= 0.f) ? v0 : LEAK * v0;
    v1 = (v1 >= 0.f) ? v1 : LEAK * v1;
    dst[i] = __halves2half2(__float2half_rn(v0), __float2half_rn(v1));
}

// ---------------------------------------------------------------------------
// 6. FUSED: instnorm-apply(+leaky) -> out_vf [b][c][vox] AND g_vfth [b][vox][c] (fp16)
// ---------------------------------------------------------------------------
__global__ void in_dual_kernel(const float* __restrict__ ss, const float* __restrict__ sq,
                               float* __restrict__ out_vf) {
    __shared__ float t[32][33];
    int b = blockIdx.z, ct = blockIdx.y, vt = blockIdx.x;
    int tx = threadIdx.x & 31, ty = threadIdx.x >> 5;
    const float* s = g_tmp + ((size_t)b*CH + ct*32)*RCUBE + vt*32;
    float* o = out_vf + ((size_t)b*CH + ct*32)*RCUBE + vt*32;
#pragma unroll
    for (int k = 0; k < 32; k += 8) {
        int c = ct*32 + ty + k;
        float m   = ss[b*CH + c] / (float)RCUBE;
        float var = fmaxf(sq[b*CH + c] / (float)RCUBE - m*m, 0.f);
        float rs  = rsqrtf(var + NORM_EPS);
        float v = (s[(size_t)(ty+k)*RCUBE + tx] - m) * rs;
        v = (v >= 0.f) ? v : LEAK * v;
        o[(size_t)(ty+k)*RCUBE + tx] = v;
        t[ty+k][tx] = v;
    }
    __syncthreads();
#pragma unroll
    for (int k = 0; k < 32; k += 8) {
        size_t di = ((size_t)b*RCUBE + vt*32 + ty + k)*CH + ct*32 + tx;
        g_vfth[di] = __float2half_rn(t[tx][ty+k]);
    }
}

// ---------------------------------------------------------------------------
// 7a. weight prep: W[co][ci][27] fp32 -> fp16 [27][co][ci]
// ---------------------------------------------------------------------------
__global__ void wprep_kernel(const float* __restrict__ W, __half* __restrict__ hi) {
    int i = blockIdx.x*256 + threadIdx.x;
    if (i >= 27*64*64) return;
    int ci = i & 63;
    int rest = i >> 6;
    int co = rest & 63, off = rest >> 6;
    hi[i] = __float2half_rn(W[((size_t)co*64 + ci)*27 + off]);
}

// ---------------------------------------------------------------------------
// 7b. Conv3d 3x3x3, single-pass fp16 mma, cp.async double-buffered pipeline.
//     CTA=(b,d,h-half), M=512, 8 warps x (M64,N64), 1 CTA/SM.
//     FP16OUT: epilogue writes fp16 channel-last (conv1); else fp32 [b][c][vox].
// ---------------------------------------------------------------------------
#define SA_BYTES (3*18*34*16*2)   // 58752
#define SW_BYTES (27*64*16*2)     // 55296
#define CONV_SMEM (2*SA_BYTES + 2*SW_BYTES)   // 228,096 bytes

__device__ __forceinline__ void conv_load_chunk(
    uint32_t sA_u32, uint32_t sW_u32, const __half* __restrict__ Whi,
    int b, int d, int h0, int ci0, int tid) {
    for (int u = tid; u < 2*3*18*34; u += 256) {
        int halfsel = u & 1, pos = u >> 1;
        int dd = pos / 612;
        int r  = pos - dd*612;
        int hy = r / 34;
        int ww = r - hy*34;
        int gd = d - 1 + dd, gh = h0 - 1 + hy, gw = ww - 1;
        bool inb = (unsigned)gd < 32u && (unsigned)gh < 32u && (unsigned)gw < 32u;
        size_t gi = inb ? ((size_t)b*RCUBE + gd*1024 + gh*32 + gw)*64 + ci0 + halfsel*8
                        : 0;
        int sz = inb ? 16 : 0;
        CP_ASYNC16(sA_u32 + u*16, g_ahi + gi, sz);
    }
    for (int u = tid; u < 2*27*64; u += 256) {
        int halfsel = u & 1, row = u >> 1;
        CP_ASYNC16(sW_u32 + u*16, Whi + (size_t)row*64 + ci0 + halfsel*8, 16);
    }
}

template<int FP16OUT>
__global__ __launch_bounds__(256, 1)
void conv_mma_kernel(const __half* __restrict__ Whi,
                     const float* __restrict__ bias,
                     float* __restrict__ out,
                     float* __restrict__ ss, float* __restrict__ sq) {
    extern __shared__ __align__(16) char smem_raw[];
    char* pA[2] = { smem_raw, smem_raw + SA_BYTES };
    char* pW[2] = { smem_raw + 2*SA_BYTES, smem_raw + 2*SA_BYTES + SW_BYTES };
    uint32_t uA[2] = { smem_u32(pA[0]), smem_u32(pA[1]) };
    uint32_t uW[2] = { smem_u32(pW[0]), smem_u32(pW[1]) };

    int bid = blockIdx.x;
    int hh = bid & 1, d = (bid >> 1) & 31, b = bid >> 6;
    int h0 = hh * 16;
    int tid = threadIdx.x;
    int warp = tid >> 5, lane = tid & 31;
    int g = lane >> 2, tg = lane & 3;

    float acc[4][8][4];
#pragma unroll
    for (int t = 0; t < 4; t++)
#pragma unroll
        for (int n = 0; n < 8; n++)
#pragma unroll
            for (int e = 0; e < 4; e++) acc[t][n][e] = 0.f;

    int abase[4];
#pragma unroll
    for (int t = 0; t < 4; t++) {
        int h_loc = warp*2 + (t >> 1);
        int wb = (t & 1)*16;
        abase[t] = (h_loc*34 + wb + g)*32 + tg*4;
    }
    int bthread = g*32 + tg*4;

    conv_load_chunk(uA[0], uW[0], Whi, b, d, h0, 0, tid);
    CP_COMMIT();
    CP_WAIT0();
    __syncthreads();

#pragma unroll 1
    for (int cq = 0; cq < 4; cq++) {
        int buf = cq & 1;
        if (cq < 3) {
            conv_load_chunk(uA[buf^1], uW[buf^1], Whi, b, d, h0, (cq+1)*16, tid);
            CP_COMMIT();
        }

        const char* sAh = pA[buf];
        const char* sWh = pW[buf];
        int dd = 0, dh = 0, dw = 0;
#pragma unroll 1
        for (int off = 0; off < 27; ++off) {
            int rowoff = ((dd*18 + dh)*34 + dw)*32;
            uint32_t ah[4][4];
#pragma unroll
            for (int t = 0; t < 4; ++t) {
                const char* pa = sAh + rowoff + abase[t];
                ah[t][0] = *(const uint32_t*)(pa);
                ah[t][2] = *(const uint32_t*)(pa + 16);
                ah[t][1] = *(const uint32_t*)(pa + 256);
                ah[t][3] = *(const uint32_t*)(pa + 272);
            }
            int bo = off*2048 + bthread;
#pragma unroll
            for (int n8 = 0; n8 < 8; ++n8) {
                const char* pbh = sWh + bo + n8*256;
                uint32_t bh0 = *(const uint32_t*)(pbh);
                uint32_t bh1 = *(const uint32_t*)(pbh + 16);
#pragma unroll
                for (int t = 0; t < 4; ++t)
                    mma_fp16(acc[t][n8], ah[t], bh0, bh1);
            }
            if (++dw == 3) { dw = 0; if (++dh == 3) { dh = 0; ++dd; } }
        }

        CP_WAIT0();
        __syncthreads();
    }

    // epilogue
#pragma unroll
    for (int n8 = 0; n8 < 8; ++n8) {
        int co0 = n8*8 + 2*tg;                  // even co of this thread's pair
        float b0 = __ldg(&bias[co0]);
        float b1 = __ldg(&bias[co0+1]);
        float s0 = 0.f, q0 = 0.f, s1 = 0.f, q1 = 0.f;
#pragma unroll
        for (int t = 0; t < 4; ++t) {
            int h_loc = warp*2 + (t >> 1);
            int wb = (t & 1)*16;
#pragma unroll
            for (int rh = 0; rh < 2; ++rh) {
                float v0 = acc[t][n8][rh*2]     + b0;
                float v1 = acc[t][n8][rh*2 + 1] + b1;
                int vox = d*1024 + (h0 + h_loc)*32 + wb + g + rh*8;
                if (FP16OUT) {
                    *(__half2*)&g_tmp16[((size_t)b*RCUBE + vox)*64 + co0] =
                        __halves2half2(__float2half_rn(v0), __float2half_rn(v1));
                } else {
                    out[((size_t)b*CH + co0    )*RCUBE + vox] = v0;
                    out[((size_t)b*CH + co0 + 1)*RCUBE + vox] = v1;
                }
                s0 += v0; q0 = fmaf(v0, v0, q0);
                s1 += v1; q1 = fmaf(v1, v1, q1);
            }
        }
#pragma unroll
        for (int o = 4; o < 32; o <<= 1) {
            s0 += __shfl_xor_sync(0xffffffffu, s0, o);
            q0 += __shfl_xor_sync(0xffffffffu, q0, o);
            s1 += __shfl_xor_sync(0xffffffffu, s1, o);
            q1 += __shfl_xor_sync(0xffffffffu, q1, o);
        }
        if (g == 0) {
            atomicAdd(&ss[b*CH + co0],     s0);
            atomicAdd(&sq[b*CH + co0],     q0);
            atomicAdd(&ss[b*CH + co0 + 1], s1);
            atomicAdd(&sq[b*CH + co0 + 1], q1);
        }
    }
}

// ---------------------------------------------------------------------------
// 8. point branch GEMM with fused IN-stat accumulation
// ---------------------------------------------------------------------------
__global__ void pointmlp_kernel(const float* __restrict__ features,
                                const float* __restrict__ pw,
                                const float* __restrict__ pb) {
    __shared__ float sw[64*64];
    __shared__ float sb[64];
    int tid = threadIdx.x;
    for (int i = tid; i < 4096; i += 256) sw[i] = pw[i];
    if (tid < 64) sb[tid] = pb[tid];
    __syncthreads();
    int blk = blockIdx.x;
    int b = blk >> 7;
    int n = (blk & 127)*256 + tid;
    float acc[64];
#pragma unroll
    for (int o = 0; o < 64; o++) acc[o] = 0.f;
    const float* f = features + (size_t)b*CH*NPTS + n;
    for (int c = 0; c < 64; c++) {
        float v = f[(size_t)c*NPTS];
#pragma unroll
        for (int o = 0; o < 64; o++) acc[o] = fmaf(sw[o*64 + c], v, acc[o]);
    }
    float* p = g_p + (size_t)b*CH*NPTS + n;
#pragma unroll
    for (int o = 0; o < 64; o++) {
        float v = acc[o] + sb[o];
        p[(size_t)o*NPTS] = v;
        float s = v, q = v*v;
        for (int off = 16; off; off >>= 1) {
            s += __shfl_xor_sync(0xffffffffu, s, off);
            q += __shfl_xor_sync(0xffffffffu, q, off);
        }
        if ((tid & 31) == 0) {
            atomicAdd(&g_psts[b*CH + o], s);
            atomicAdd(&g_pstq[b*CH + o], q);
        }
    }
}

// ---------------------------------------------------------------------------
// 9. FUSED final: trilinear devoxelize (fp16 gather) + point-norm + add -> out
// ---------------------------------------------------------------------------
__global__ void final_kernel(float* __restrict__ outf) {
    __shared__ float t[32][65];
    int blk = blockIdx.x;
    int b = blk >> 10;
    int n0 = (blk & 1023)*32;
    int tid = threadIdx.x;
    int warp = tid >> 5, lane = tid & 31;

#pragma unroll
    for (int j = 0; j < 4; j++) {
        int nl = warp*4 + j;
        int n = n0 + nl;
        float nx = g_nc[((size_t)b*3 + 0)*NPTS + n];
        float ny = g_nc[((size_t)b*3 + 1)*NPTS + n];
        float nz = g_nc[((size_t)b*3 + 2)*NPTS + n];
        int lx = (int)floorf(nx), ly = (int)floorf(ny), lz = (int)floorf(nz);
        float fx = nx - (float)lx, fy = ny - (float)ly, fz = nz - (float)lz;
        int hx = min(lx+1, 31), hy = min(ly+1, 31), hz = min(lz+1, 31);
        const __half* base = g_vfth + (size_t)b*RCUBE*CH;
        float a0 = 0.f, a1 = 0.f;
#pragma unroll
        for (int k = 0; k < 8; k++) {
            int dx = k >> 2, dy = (k >> 1) & 1, dz = k & 1;
            int ix = dx ? hx : lx, iy = dy ? hy : ly, iz = dz ? hz : lz;
            float wgt = (dx ? fx : 1.f-fx) * (dy ? fy : 1.f-fy) * (dz ? fz : 1.f-fz);
            const __half2* p = (const __half2*)(base + (size_t)(ix*1024 + iy*32 + iz)*CH);
            float2 f2 = __half22float2(p[lane]);
            a0 = fmaf(wgt, f2.x, a0);
            a1 = fmaf(wgt, f2.y, a1);
        }
        t[nl][2*lane]     = a0;
        t[nl][2*lane + 1] = a1;
    }
    __syncthreads();

    size_t ob = (size_t)b*CH*NPTS + n0;
    for (int i = tid; i < 2048; i += 256) {
        int nl = i & 31, c = i >> 5;
        float m   = g_psts[b*CH + c] / (float)NPTS;
        float var = fmaxf(g_pstq[b*CH + c] / (float)NPTS - m*m, 0.f);
        float rs  = rsqrtf(var + NORM_EPS);
        size_t o = ob + (size_t)c*NPTS + nl;
        float v = (g_p[o] - m) * rs;
        v = (v >= 0.f) ? v : LEAK * v;
        outf[o] = t[nl][c] + v;
    }
}

// ---------------------------------------------------------------------------
// launch
// ---------------------------------------------------------------------------
extern "C" void kernel_launch(void* const* d_in, const int* in_sizes, int n_in,
                              void* d_out, int out_size) {
    const float* features = (const float*)d_in[0];
    const float* coords   = (const float*)d_in[1];
    const float* c1w      = (const float*)d_in[2];
    const float* c1b      = (const float*)d_in[3];
    const float* c2w      = (const float*)d_in[4];
    const float* c2b      = (const float*)d_in[5];
    const float* pw       = (const float*)d_in[6];
    const float* pb       = (const float*)d_in[7];
    float* out = (float*)d_out;
    float* out_fused  = out + OFF_FUSED;
    float* out_coords = out + OFF_COORDS;
    float* out_vf     = out + OFF_VF;

    float *p_tmp, *p_sums, *p_cnt;
    float *p_s1s, *p_s1q, *p_s2s, *p_s2q;
    __half *p_w1h, *p_w2h;
    cudaGetSymbolAddress((void**)&p_tmp,  g_tmp);
    cudaGetSymbolAddress((void**)&p_sums, g_sums);
    cudaGetSymbolAddress((void**)&p_cnt,  g_cnt);
    cudaGetSymbolAddress((void**)&p_s1s,  g_st1s);
    cudaGetSymbolAddress((void**)&p_s1q,  g_st1q);
    cudaGetSymbolAddress((void**)&p_s2s,  g_st2s);
    cudaGetSymbolAddress((void**)&p_s2q,  g_st2q);
    cudaGetSymbolAddress((void**)&p_w1h,  g_w1h);
    cudaGetSymbolAddress((void**)&p_w2h,  g_w2h);

    cudaFuncSetAttribute(conv_mma_kernel<1>,
                         cudaFuncAttributeMaxDynamicSharedMemorySize, CONV_SMEM);
    cudaFuncSetAttribute(conv_mma_kernel<0>,
                         cudaFuncAttributeMaxDynamicSharedMemorySize, CONV_SMEM);

    cudaMemsetAsync(p_sums, 0, (size_t)GRID_ELEMS*sizeof(float));
    cudaMemsetAsync(p_cnt,  0, (size_t)BATCH*RCUBE*sizeof(float));
    zero_stats_kernel<<<2, 256>>>();
    meannorm_kernel<<<BATCH, 256>>>(coords);
    voxscatter_kernel<<<BATCH*NPTS/256, 256>>>(coords, features);

    wprep_kernel<<<(27*64*64 + 255)/256, 256>>>(c1w, p_w1h);
    wprep_kernel<<<(27*64*64 + 255)/256, 256>>>(c2w, p_w2h);

    pointmlp_kernel<<<BATCH*128, 256>>>(features, pw, pb);

    // conv1 (fp16 channel-last out)
    avg_aprep_kernel<<<GRID_ELEMS/4/256, 256>>>();
    conv_mma_kernel<1><<<BATCH*32*2, 256, CONV_SMEM>>>(p_w1h, c1b, nullptr, p_s1s, p_s1q);
    in_aprep_kernel<<<dim3(RCUBE*CH/2/256, BATCH), 256>>>(p_s1s, p_s1q);
    // conv2 (fp32 out)
    conv_mma_kernel<0><<<BATCH*32*2, 256, CONV_SMEM>>>(p_w2h, c2b, p_tmp, p_s2s, p_s2q);
    in_dual_kernel<<<dim3(1024, 2, BATCH), 256>>>(p_s2s, p_s2q, out_vf);

    final_kernel<<<BATCH*1024, 256>>>(out_fused);

    cudaMemcpyAsync(out_coords, coords, (size_t)BATCH*3*NPTS*sizeof(float),
                    cudaMemcpyDeviceToDevice);
}

// round 16
// speedup vs baseline: 1.0086x; 1.0086x over previous
#include <cuda_runtime.h>
#include <cuda_fp16.h>
#include <cstddef>
#include <cstdint>

// ---------------------------------------------------------------------------
// Problem constants
// ---------------------------------------------------------------------------
#define BATCH   8
#define CH      64
#define NPTS    32768
#define RES     32
#define RCUBE   32768
#define GRID_ELEMS (BATCH*CH*RCUBE)
#define LEAK    0.1f
#define NORM_EPS 1e-4f

#define OFF_FUSED   0
#define OFF_COORDS  (BATCH*CH*NPTS)
#define OFF_VF      (OFF_COORDS + BATCH*3*NPTS)

// ---------------------------------------------------------------------------
// Scratch
// ---------------------------------------------------------------------------
__device__ float g_sums[GRID_ELEMS];     // CHANNEL-LAST: [b][vox][64c]
__device__ float g_cnt [BATCH*RCUBE];
__device__ float g_tmp [GRID_ELEMS];     // conv raw out, [b][c][vox] fp32
__device__ float g_nc  [BATCH*3*NPTS];
__device__ float g_mean[BATCH*3];
__device__ float g_denom[BATCH];
__device__ float g_st1s[BATCH*CH];
__device__ float g_st1q[BATCH*CH];
__device__ float g_st2s[BATCH*CH];
__device__ float g_st2q[BATCH*CH];
__device__ float g_psts[BATCH*CH];
__device__ float g_pstq[BATCH*CH];

// fp16 staging
__device__ __align__(16) __half g_ahi[GRID_ELEMS];   // conv input, [b][vox][c]
__device__ __align__(16) __half g_w1h[27*64*64];
__device__ __align__(16) __half g_w2h[27*64*64];
__device__ __align__(16) __half g_vfth[GRID_ELEMS];  // voxel feats, [b][vox][c]
__device__ __align__(16) __half g_p16[GRID_ELEMS];   // point branch pre-norm, [b][c][n]

// ---------------------------------------------------------------------------
// mma.m16n8k16 fp16 -> fp32
// ---------------------------------------------------------------------------
__device__ __forceinline__ void mma_fp16(float* d, const uint32_t* a,
                                         uint32_t b0, uint32_t b1) {
    asm volatile(
        "mma.sync.aligned.m16n8k16.row.col.f32.f16.f16.f32 "
        "{%0,%1,%2,%3}, {%4,%5,%6,%7}, {%8,%9}, {%0,%1,%2,%3};"
        : "+f"(d[0]), "+f"(d[1]), "+f"(d[2]), "+f"(d[3])
        : "r"(a[0]), "r"(a[1]), "r"(a[2]), "r"(a[3]), "r"(b0), "r"(b1));
}

__device__ __forceinline__ void red_add_v4(float* p, float a, float b, float c, float d) {
    asm volatile("red.global.add.v4.f32 [%0], {%1,%2,%3,%4};"
                 :: "l"(p), "f"(a), "f"(b), "f"(c), "f"(d) : "memory");
}

__device__ __forceinline__ uint32_t smem_u32(const void* p) {
    uint32_t a;
    asm("{ .reg .u64 t; cvta.to.shared.u64 t, %1; cvt.u32.u64 %0, t; }"
        : "=r"(a) : "l"(p));
    return a;
}

#define CP_ASYNC16(dst, src, sz) \
    asm volatile("cp.async.cg.shared.global [%0], [%1], 16, %2;" \
                 :: "r"(dst), "l"(src), "r"(sz) : "memory")
#define CP_COMMIT() asm volatile("cp.async.commit_group;" ::: "memory")
#define CP_WAIT0()  asm volatile("cp.async.wait_group 0;" ::: "memory")

// ---------------------------------------------------------------------------
// 0. zero per-(b,c) stats (bulk arrays zeroed via cudaMemsetAsync)
// ---------------------------------------------------------------------------
__global__ void zero_stats_kernel() {
    int t = blockIdx.x*blockDim.x + threadIdx.x;
    if (t < BATCH*CH) {
        g_st1s[t] = 0.f; g_st1q[t] = 0.f;
        g_st2s[t] = 0.f; g_st2q[t] = 0.f;
        g_psts[t] = 0.f; g_pstq[t] = 0.f;
    }
}

// ---------------------------------------------------------------------------
// 1. per-batch coordinate mean + max point norm (merged)
// ---------------------------------------------------------------------------
__global__ void meannorm_kernel(const float* __restrict__ coords) {
    int b = blockIdx.x, tid = threadIdx.x;
    const float* cb = coords + (size_t)b*3*NPTS;
    float s0 = 0.f, s1 = 0.f, s2 = 0.f;
    for (int n = tid; n < NPTS; n += 256) {
        s0 += cb[n]; s1 += cb[NPTS + n]; s2 += cb[2*NPTS + n];
    }
    for (int o = 16; o; o >>= 1) {
        s0 += __shfl_xor_sync(0xffffffffu, s0, o);
        s1 += __shfl_xor_sync(0xffffffffu, s1, o);
        s2 += __shfl_xor_sync(0xffffffffu, s2, o);
    }
    __shared__ float sh[3][8];
    __shared__ float sm0, sm1, sm2;
    int w = tid >> 5;
    if ((tid & 31) == 0) { sh[0][w] = s0; sh[1][w] = s1; sh[2][w] = s2; }
    __syncthreads();
    if (tid == 0) {
        float t0 = 0.f, t1 = 0.f, t2 = 0.f;
        for (int i = 0; i < 8; i++) { t0 += sh[0][i]; t1 += sh[1][i]; t2 += sh[2][i]; }
        sm0 = t0 / (float)NPTS;
        sm1 = t1 / (float)NPTS;
        sm2 = t2 / (float)NPTS;
        g_mean[b*3+0] = sm0;
        g_mean[b*3+1] = sm1;
        g_mean[b*3+2] = sm2;
    }
    __syncthreads();
    float m0 = sm0, m1 = sm1, m2 = sm2;
    float mx = 0.f;
    for (int n = tid; n < NPTS; n += 256) {
        float dx = cb[n] - m0, dy = cb[NPTS+n] - m1, dz = cb[2*NPTS+n] - m2;
        float sq = dx*dx + dy*dy + dz*dz;
        mx = fmaxf(mx, sq);
    }
    for (int o = 16; o; o >>= 1) mx = fmaxf(mx, __shfl_xor_sync(0xffffffffu, mx, o));
    __shared__ float shm[8];
    if ((tid & 31) == 0) shm[w] = mx;
    __syncthreads();
    if (tid == 0) {
        float t = 0.f;
        for (int i = 0; i < 8; i++) t = fmaxf(t, shm[i]);
        g_denom[b] = 2.0f * sqrtf(t);
    }
}

// ---------------------------------------------------------------------------
// 2. norm_coords + scatter-add (channel-last sums, v4 vector reductions)
// ---------------------------------------------------------------------------
__global__ void voxscatter_kernel(const float* __restrict__ coords,
                                  const float* __restrict__ features) {
    int t = blockIdx.x*blockDim.x + threadIdx.x;
    int b = t >> 15, n = t & (NPTS-1);
    float den = g_denom[b];
    int vi[3];
#pragma unroll
    for (int d = 0; d < 3; d++) {
        float c = coords[((size_t)b*3 + d)*NPTS + n];
        float v = (c - g_mean[b*3+d]) / den + 0.5f;
        v *= (float)RES;
        v = fminf(fmaxf(v, 0.f), (float)(RES-1));
        g_nc[((size_t)b*3 + d)*NPTS + n] = v;
        vi[d] = (int)rintf(v);
    }
    int vox = vi[0]*RES*RES + vi[1]*RES + vi[2];
    atomicAdd(&g_cnt[b*RCUBE + vox], 1.f);
    size_t fb = (size_t)b*CH*NPTS + n;
    size_t sb = ((size_t)b*RCUBE + vox)*64;
#pragma unroll 4
    for (int c = 0; c < CH; c += 4) {
        float v0 = features[fb + (size_t)(c+0)*NPTS];
        float v1 = features[fb + (size_t)(c+1)*NPTS];
        float v2 = features[fb + (size_t)(c+2)*NPTS];
        float v3 = features[fb + (size_t)(c+3)*NPTS];
        red_add_v4(&g_sums[sb + c], v0, v1, v2, v3);
    }
}

// ---------------------------------------------------------------------------
// 3. FUSED: average + fp16 convert (conv1 input prep), pure streaming
// ---------------------------------------------------------------------------
__global__ void avg_aprep_kernel() {
    int i = blockIdx.x*256 + threadIdx.x;
    int bv = i >> 4;
    float cv = fmaxf(g_cnt[bv], 1.f);
    float4 v = ((const float4*)g_sums)[i];
    ((__half2*)g_ahi)[i*2    ] = __halves2half2(__float2half_rn(v.x / cv),
                                                __float2half_rn(v.y / cv));
    ((__half2*)g_ahi)[i*2 + 1] = __halves2half2(__float2half_rn(v.z / cv),
                                                __float2half_rn(v.w / cv));
}

// ---------------------------------------------------------------------------
// 4. FUSED: instnorm-apply(+leaky) + channel-last fp16 convert (conv2 input prep)
// ---------------------------------------------------------------------------
__global__ void in_aprep_kernel(const float* __restrict__ ss, const float* __restrict__ sq) {
    __shared__ float t[32][33];
    int b = blockIdx.z, ct = blockIdx.y, vt = blockIdx.x;
    int tx = threadIdx.x & 31, ty = threadIdx.x >> 5;
    const float* s = g_tmp + ((size_t)b*CH + ct*32)*RCUBE + vt*32;
#pragma unroll
    for (int k = 0; k < 32; k += 8) {
        int c = ct*32 + ty + k;
        float m   = ss[b*CH + c] / (float)RCUBE;
        float var = fmaxf(sq[b*CH + c] / (float)RCUBE - m*m, 0.f);
        float rs  = rsqrtf(var + NORM_EPS);
        float v = (s[(size_t)(ty+k)*RCUBE + tx] - m) * rs;
        t[ty+k][tx] = (v >= 0.f) ? v : LEAK * v;
    }
    __syncthreads();
#pragma unroll
    for (int k = 0; k < 32; k += 8) {
        size_t di = ((size_t)b*RCUBE + vt*32 + ty + k)*CH + ct*32 + tx;
        g_ahi[di] = __float2half_rn(t[tx][ty+k]);
    }
}

// ---------------------------------------------------------------------------
// 5. FUSED: instnorm-apply(+leaky) -> out_vf [b][c][vox] AND g_vfth [b][vox][c] (fp16)
// ---------------------------------------------------------------------------
__global__ void in_dual_kernel(const float* __restrict__ ss, const float* __restrict__ sq,
                               float* __restrict__ out_vf) {
    __shared__ float t[32][33];
    int b = blockIdx.z, ct = blockIdx.y, vt = blockIdx.x;
    int tx = threadIdx.x & 31, ty = threadIdx.x >> 5;
    const float* s = g_tmp + ((size_t)b*CH + ct*32)*RCUBE + vt*32;
    float* o = out_vf + ((size_t)b*CH + ct*32)*RCUBE + vt*32;
#pragma unroll
    for (int k = 0; k < 32; k += 8) {
        int c = ct*32 + ty + k;
        float m   = ss[b*CH + c] / (float)RCUBE;
        float var = fmaxf(sq[b*CH + c] / (float)RCUBE - m*m, 0.f);
        float rs  = rsqrtf(var + NORM_EPS);
        float v = (s[(size_t)(ty+k)*RCUBE + tx] - m) * rs;
        v = (v >= 0.f) ? v : LEAK * v;
        o[(size_t)(ty+k)*RCUBE + tx] = v;
        t[ty+k][tx] = v;
    }
    __syncthreads();
#pragma unroll
    for (int k = 0; k < 32; k += 8) {
        size_t di = ((size_t)b*RCUBE + vt*32 + ty + k)*CH + ct*32 + tx;
        g_vfth[di] = __float2half_rn(t[tx][ty+k]);
    }
}

// ---------------------------------------------------------------------------
// 6a. weight prep: W[co][ci][27] fp32 -> fp16 [27][co][ci]
// ---------------------------------------------------------------------------
__global__ void wprep_kernel(const float* __restrict__ W, __half* __restrict__ hi) {
    int i = blockIdx.x*256 + threadIdx.x;
    if (i >= 27*64*64) return;
    int ci = i & 63;
    int rest = i >> 6;
    int co = rest & 63, off = rest >> 6;
    hi[i] = __float2half_rn(W[((size_t)co*64 + ci)*27 + off]);
}

// ---------------------------------------------------------------------------
// 6b. Conv3d 3x3x3, single-pass fp16 mma, cp.async double-buffered (R14 best).
//     CTA=(b,d,h-half), M=512, 8 warps x (M64,N64), 1 CTA/SM.
// ---------------------------------------------------------------------------
#define SA_BYTES (3*18*34*16*2)   // 58752
#define SW_BYTES (27*64*16*2)     // 55296
#define CONV_SMEM (2*SA_BYTES + 2*SW_BYTES)   // 228,096 bytes

__device__ __forceinline__ void conv_load_chunk(
    uint32_t sA_u32, uint32_t sW_u32, const __half* __restrict__ Whi,
    int b, int d, int h0, int ci0, int tid) {
    for (int u = tid; u < 2*3*18*34; u += 256) {
        int halfsel = u & 1, pos = u >> 1;
        int dd = pos / 612;
        int r  = pos - dd*612;
        int hy = r / 34;
        int ww = r - hy*34;
        int gd = d - 1 + dd, gh = h0 - 1 + hy, gw = ww - 1;
        bool inb = (unsigned)gd < 32u && (unsigned)gh < 32u && (unsigned)gw < 32u;
        size_t gi = inb ? ((size_t)b*RCUBE + gd*1024 + gh*32 + gw)*64 + ci0 + halfsel*8
                        : 0;
        int sz = inb ? 16 : 0;
        CP_ASYNC16(sA_u32 + u*16, g_ahi + gi, sz);
    }
    for (int u = tid; u < 2*27*64; u += 256) {
        int halfsel = u & 1, row = u >> 1;
        CP_ASYNC16(sW_u32 + u*16, Whi + (size_t)row*64 + ci0 + halfsel*8, 16);
    }
}

__global__ __launch_bounds__(256, 1)
void conv_mma_kernel(const __half* __restrict__ Whi,
                     const float* __restrict__ bias,
                     float* __restrict__ out,
                     float* __restrict__ ss, float* __restrict__ sq) {
    extern __shared__ __align__(16) char smem_raw[];
    char* pA[2] = { smem_raw, smem_raw + SA_BYTES };
    char* pW[2] = { smem_raw + 2*SA_BYTES, smem_raw + 2*SA_BYTES + SW_BYTES };
    uint32_t uA[2] = { smem_u32(pA[0]), smem_u32(pA[1]) };
    uint32_t uW[2] = { smem_u32(pW[0]), smem_u32(pW[1]) };

    int bid = blockIdx.x;
    int hh = bid & 1, d = (bid >> 1) & 31, b = bid >> 6;
    int h0 = hh * 16;
    int tid = threadIdx.x;
    int warp = tid >> 5, lane = tid & 31;
    int g = lane >> 2, tg = lane & 3;

    float acc[4][8][4];
#pragma unroll
    for (int t = 0; t < 4; t++)
#pragma unroll
        for (int n = 0; n < 8; n++)
#pragma unroll
            for (int e = 0; e < 4; e++) acc[t][n][e] = 0.f;

    int abase[4];
#pragma unroll
    for (int t = 0; t < 4; t++) {
        int h_loc = warp*2 + (t >> 1);
        int wb = (t & 1)*16;
        abase[t] = (h_loc*34 + wb + g)*32 + tg*4;
    }
    int bthread = g*32 + tg*4;

    conv_load_chunk(uA[0], uW[0], Whi, b, d, h0, 0, tid);
    CP_COMMIT();
    CP_WAIT0();
    __syncthreads();

#pragma unroll 1
    for (int cq = 0; cq < 4; cq++) {
        int buf = cq & 1;
        if (cq < 3) {
            conv_load_chunk(uA[buf^1], uW[buf^1], Whi, b, d, h0, (cq+1)*16, tid);
            CP_COMMIT();
        }

        const char* sAh = pA[buf];
        const char* sWh = pW[buf];
        int dd = 0, dh = 0, dw = 0;
#pragma unroll 1
        for (int off = 0; off < 27; ++off) {
            int rowoff = ((dd*18 + dh)*34 + dw)*32;
            uint32_t ah[4][4];
#pragma unroll
            for (int t = 0; t < 4; ++t) {
                const char* pa = sAh + rowoff + abase[t];
                ah[t][0] = *(const uint32_t*)(pa);
                ah[t][2] = *(const uint32_t*)(pa + 16);
                ah[t][1] = *(const uint32_t*)(pa + 256);
                ah[t][3] = *(const uint32_t*)(pa + 272);
            }
            int bo = off*2048 + bthread;
#pragma unroll
            for (int n8 = 0; n8 < 8; ++n8) {
                const char* pbh = sWh + bo + n8*256;
                uint32_t bh0 = *(const uint32_t*)(pbh);
                uint32_t bh1 = *(const uint32_t*)(pbh + 16);
#pragma unroll
                for (int t = 0; t < 4; ++t)
                    mma_fp16(acc[t][n8], ah[t], bh0, bh1);
            }
            if (++dw == 3) { dw = 0; if (++dh == 3) { dh = 0; ++dd; } }
        }

        CP_WAIT0();
        __syncthreads();
    }

    // epilogue: bias, store fp32 [b][c][vox], fused IN stats
#pragma unroll
    for (int n8 = 0; n8 < 8; ++n8) {
#pragma unroll
        for (int par = 0; par < 2; ++par) {
            int co = n8*8 + 2*tg + par;
            float bb = __ldg(&bias[co]);
            float s = 0.f, q = 0.f;
            size_t obase = ((size_t)b*CH + co)*RCUBE + d*1024;
#pragma unroll
            for (int t = 0; t < 4; ++t) {
                int h_loc = warp*2 + (t >> 1);
                int wb = (t & 1)*16;
#pragma unroll
                for (int rh = 0; rh < 2; ++rh) {
                    float v = acc[t][n8][rh*2 + par] + bb;
                    out[obase + (h0 + h_loc)*32 + wb + g + rh*8] = v;
                    s += v;
                    q = fmaf(v, v, q);
                }
            }
            s += __shfl_xor_sync(0xffffffffu, s, 4);
            q += __shfl_xor_sync(0xffffffffu, q, 4);
            s += __shfl_xor_sync(0xffffffffu, s, 8);
            q += __shfl_xor_sync(0xffffffffu, q, 8);
            s += __shfl_xor_sync(0xffffffffu, s, 16);
            q += __shfl_xor_sync(0xffffffffu, q, 16);
            if (g == 0) {
                atomicAdd(&ss[b*CH + co], s);
                atomicAdd(&sq[b*CH + co], q);
            }
        }
    }
}

// ---------------------------------------------------------------------------
// 7. point branch GEMM, fp16 output + fused IN-stat accumulation
// ---------------------------------------------------------------------------
__global__ void pointmlp_kernel(const float* __restrict__ features,
                                const float* __restrict__ pw,
                                const float* __restrict__ pb) {
    __shared__ float sw[64*64];
    __shared__ float sb[64];
    int tid = threadIdx.x;
    for (int i = tid; i < 4096; i += 256) sw[i] = pw[i];
    if (tid < 64) sb[tid] = pb[tid];
    __syncthreads();
    int blk = blockIdx.x;
    int b = blk >> 7;
    int n = (blk & 127)*256 + tid;
    float acc[64];
#pragma unroll
    for (int o = 0; o < 64; o++) acc[o] = 0.f;
    const float* f = features + (size_t)b*CH*NPTS + n;
    for (int c = 0; c < 64; c++) {
        float v = f[(size_t)c*NPTS];
#pragma unroll
        for (int o = 0; o < 64; o++) acc[o] = fmaf(sw[o*64 + c], v, acc[o]);
    }
    __half* p = g_p16 + (size_t)b*CH*NPTS + n;
#pragma unroll
    for (int o = 0; o < 64; o++) {
        float v = acc[o] + sb[o];
        p[(size_t)o*NPTS] = __float2half_rn(v);
        float s = v, q = v*v;
        for (int off = 16; off; off >>= 1) {
            s += __shfl_xor_sync(0xffffffffu, s, off);
            q += __shfl_xor_sync(0xffffffffu, q, off);
        }
        if ((tid & 31) == 0) {
            atomicAdd(&g_psts[b*CH + o], s);
            atomicAdd(&g_pstq[b*CH + o], q);
        }
    }
}

// ---------------------------------------------------------------------------
// 8. FUSED final: trilinear devoxelize (fp16 gather) + point-norm + add -> out
// ---------------------------------------------------------------------------
__global__ void final_kernel(float* __restrict__ outf) {
    __shared__ float t[32][65];
    int blk = blockIdx.x;
    int b = blk >> 10;
    int n0 = (blk & 1023)*32;
    int tid = threadIdx.x;
    int warp = tid >> 5, lane = tid & 31;

#pragma unroll
    for (int j = 0; j < 4; j++) {
        int nl = warp*4 + j;
        int n = n0 + nl;
        float nx = g_nc[((size_t)b*3 + 0)*NPTS + n];
        float ny = g_nc[((size_t)b*3 + 1)*NPTS + n];
        float nz = g_nc[((size_t)b*3 + 2)*NPTS + n];
        int lx = (int)floorf(nx), ly = (int)floorf(ny), lz = (int)floorf(nz);
        float fx = nx - (float)lx, fy = ny - (float)ly, fz = nz - (float)lz;
        int hx = min(lx+1, 31), hy = min(ly+1, 31), hz = min(lz+1, 31);
        const __half* base = g_vfth + (size_t)b*RCUBE*CH;
        float a0 = 0.f, a1 = 0.f;
#pragma unroll
        for (int k = 0; k < 8; k++) {
            int dx = k >> 2, dy = (k >> 1) & 1, dz = k & 1;
            int ix = dx ? hx : lx, iy = dy ? hy : ly, iz = dz ? hz : lz;
            float wgt = (dx ? fx : 1.f-fx) * (dy ? fy : 1.f-fy) * (dz ? fz : 1.f-fz);
            const __half2* p = (const __half2*)(base + (size_t)(ix*1024 + iy*32 + iz)*CH);
            float2 f2 = __half22float2(p[lane]);
            a0 = fmaf(wgt, f2.x, a0);
            a1 = fmaf(wgt, f2.y, a1);
        }
        t[nl][2*lane]     = a0;
        t[nl][2*lane + 1] = a1;
    }
    __syncthreads();

    size_t ob = (size_t)b*CH*NPTS + n0;
    for (int i = tid; i < 2048; i += 256) {
        int nl = i & 31, c = i >> 5;
        float m   = g_psts[b*CH + c] / (float)NPTS;
        float var = fmaxf(g_pstq[b*CH + c] / (float)NPTS - m*m, 0.f);
        float rs  = rsqrtf(var + NORM_EPS);
        size_t o = ob + (size_t)c*NPTS + nl;
        float v = (__half2float(g_p16[o]) - m) * rs;
        v = (v >= 0.f) ? v : LEAK * v;
        outf[o] = t[nl][c] + v;
    }
}

// ---------------------------------------------------------------------------
// launch
// ---------------------------------------------------------------------------
extern "C" void kernel_launch(void* const* d_in, const int* in_sizes, int n_in,
                              void* d_out, int out_size) {
    const float* features = (const float*)d_in[0];
    const float* coords   = (const float*)d_in[1];
    const float* c1w      = (const float*)d_in[2];
    const float* c1b      = (const float*)d_in[3];
    const float* c2w      = (const float*)d_in[4];
    const float* c2b      = (const float*)d_in[5];
    const float* pw       = (const float*)d_in[6];
    const float* pb       = (const float*)d_in[7];
    float* out = (float*)d_out;
    float* out_fused  = out + OFF_FUSED;
    float* out_coords = out + OFF_COORDS;
    float* out_vf     = out + OFF_VF;

    float *p_tmp, *p_sums, *p_cnt, *p_h;
    float *p_s1s, *p_s1q, *p_s2s, *p_s2q;
    __half *p_w1h, *p_w2h;
    cudaGetSymbolAddress((void**)&p_tmp,  g_tmp);
    cudaGetSymbolAddress((void**)&p_sums, g_sums);
    cudaGetSymbolAddress((void**)&p_cnt,  g_cnt);
    cudaGetSymbolAddress((void**)&p_s1s,  g_st1s);
    cudaGetSymbolAddress((void**)&p_s1q,  g_st1q);
    cudaGetSymbolAddress((void**)&p_s2s,  g_st2s);
    cudaGetSymbolAddress((void**)&p_s2q,  g_st2q);
    cudaGetSymbolAddress((void**)&p_w1h,  g_w1h);
    cudaGetSymbolAddress((void**)&p_w2h,  g_w2h);

    cudaFuncSetAttribute(conv_mma_kernel,
                         cudaFuncAttributeMaxDynamicSharedMemorySize, CONV_SMEM);

    cudaMemsetAsync(p_sums, 0, (size_t)GRID_ELEMS*sizeof(float));
    cudaMemsetAsync(p_cnt,  0, (size_t)BATCH*RCUBE*sizeof(float));
    zero_stats_kernel<<<2, 256>>>();
    meannorm_kernel<<<BATCH, 256>>>(coords);
    voxscatter_kernel<<<BATCH*NPTS/256, 256>>>(coords, features);

    wprep_kernel<<<(27*64*64 + 255)/256, 256>>>(c1w, p_w1h);
    wprep_kernel<<<(27*64*64 + 255)/256, 256>>>(c2w, p_w2h);

    pointmlp_kernel<<<BATCH*128, 256>>>(features, pw, pb);

    // conv1
    avg_aprep_kernel<<<GRID_ELEMS/4/256, 256>>>();
    conv_mma_kernel<<<BATCH*32*2, 256, CONV_SMEM>>>(p_w1h, c1b, p_tmp, p_s1s, p_s1q);
    in_aprep_kernel<<<dim3(1024, 2, BATCH), 256>>>(p_s1s, p_s1q);
    // conv2
    conv_mma_kernel<<<BATCH*32*2, 256, CONV_SMEM>>>(p_w2h, c2b, p_tmp, p_s2s, p_s2q);
    in_dual_kernel<<<dim3(1024, 2, BATCH), 256>>>(p_s2s, p_s2q, out_vf);

    final_kernel<<<BATCH*1024, 256>>>(out_fused);

    cudaMemcpyAsync(out_coords, coords, (size_t)BATCH*3*NPTS*sizeof(float),
                    cudaMemcpyDeviceToDevice);
}

// round 17
// speedup vs baseline: 1.0372x; 1.0284x over previous
#include <cuda_runtime.h>
#include <cuda_fp16.h>
#include <cstddef>
#include <cstdint>

// ---------------------------------------------------------------------------
// Problem constants
// ---------------------------------------------------------------------------
#define BATCH   8
#define CH      64
#define NPTS    32768
#define RES     32
#define RCUBE   32768
#define GRID_ELEMS (BATCH*CH*RCUBE)
#define LEAK    0.1f
#define NORM_EPS 1e-4f

#define OFF_FUSED   0
#define OFF_COORDS  (BATCH*CH*NPTS)
#define OFF_VF      (OFF_COORDS + BATCH*3*NPTS)

// ---------------------------------------------------------------------------
// Scratch
// ---------------------------------------------------------------------------
__device__ float g_sums[GRID_ELEMS];     // CHANNEL-LAST: [b][vox][64c]
__device__ float g_cnt [BATCH*RCUBE];
__device__ float g_tmp [GRID_ELEMS];     // conv raw out, [b][c][vox] fp32
__device__ float g_nc  [BATCH*3*NPTS];
__device__ float g_mean[BATCH*3];
__device__ float g_denom[BATCH];
__device__ float g_st1s[BATCH*CH];
__device__ float g_st1q[BATCH*CH];
__device__ float g_st2s[BATCH*CH];
__device__ float g_st2q[BATCH*CH];
__device__ float g_psts[BATCH*CH];
__device__ float g_pstq[BATCH*CH];

// fp16 staging
__device__ __align__(16) __half g_ahi[GRID_ELEMS];   // conv input, [b][vox][c]
__device__ __align__(16) __half g_w1h[27*64*64];
__device__ __align__(16) __half g_w2h[27*64*64];
__device__ __align__(16) __half g_vfth[GRID_ELEMS];  // voxel feats, [b][vox][c]
__device__ __align__(16) __half g_p16[GRID_ELEMS];   // point branch pre-norm, [b][c][n]

// ---------------------------------------------------------------------------
// mma.m16n8k16 fp16 -> fp32
// ---------------------------------------------------------------------------
__device__ __forceinline__ void mma_fp16(float* d, const uint32_t* a,
                                         uint32_t b0, uint32_t b1) {
    asm volatile(
        "mma.sync.aligned.m16n8k16.row.col.f32.f16.f16.f32 "
        "{%0,%1,%2,%3}, {%4,%5,%6,%7}, {%8,%9}, {%0,%1,%2,%3};"
        : "+f"(d[0]), "+f"(d[1]), "+f"(d[2]), "+f"(d[3])
        : "r"(a[0]), "r"(a[1]), "r"(a[2]), "r"(a[3]), "r"(b0), "r"(b1));
}

__device__ __forceinline__ void red_add_v4(float* p, float a, float b, float c, float d) {
    asm volatile("red.global.add.v4.f32 [%0], {%1,%2,%3,%4};"
                 :: "l"(p), "f"(a), "f"(b), "f"(c), "f"(d) : "memory");
}

__device__ __forceinline__ uint32_t smem_u32(const void* p) {
    uint32_t a;
    asm("{ .reg .u64 t; cvta.to.shared.u64 t, %1; cvt.u32.u64 %0, t; }"
        : "=r"(a) : "l"(p));
    return a;
}

#define CP_ASYNC16(dst, src, sz) \
    asm volatile("cp.async.cg.shared.global [%0], [%1], 16, %2;" \
                 :: "r"(dst), "l"(src), "r"(sz) : "memory")
#define CP_COMMIT() asm volatile("cp.async.commit_group;" ::: "memory")
#define CP_WAIT0()  asm volatile("cp.async.wait_group 0;" ::: "memory")

// ---------------------------------------------------------------------------
// 0. zero per-(b,c) stats
// ---------------------------------------------------------------------------
__global__ void zero_stats_kernel() {
    int t = blockIdx.x*blockDim.x + threadIdx.x;
    if (t < BATCH*CH) {
        g_st1s[t] = 0.f; g_st1q[t] = 0.f;
        g_st2s[t] = 0.f; g_st2q[t] = 0.f;
        g_psts[t] = 0.f; g_pstq[t] = 0.f;
    }
}

// ---------------------------------------------------------------------------
// 1. per-batch coordinate mean + max point norm (merged)
// ---------------------------------------------------------------------------
__global__ void meannorm_kernel(const float* __restrict__ coords) {
    int b = blockIdx.x, tid = threadIdx.x;
    const float* cb = coords + (size_t)b*3*NPTS;
    float s0 = 0.f, s1 = 0.f, s2 = 0.f;
    for (int n = tid; n < NPTS; n += 256) {
        s0 += cb[n]; s1 += cb[NPTS + n]; s2 += cb[2*NPTS + n];
    }
    for (int o = 16; o; o >>= 1) {
        s0 += __shfl_xor_sync(0xffffffffu, s0, o);
        s1 += __shfl_xor_sync(0xffffffffu, s1, o);
        s2 += __shfl_xor_sync(0xffffffffu, s2, o);
    }
    __shared__ float sh[3][8];
    __shared__ float sm0, sm1, sm2;
    int w = tid >> 5;
    if ((tid & 31) == 0) { sh[0][w] = s0; sh[1][w] = s1; sh[2][w] = s2; }
    __syncthreads();
    if (tid == 0) {
        float t0 = 0.f, t1 = 0.f, t2 = 0.f;
        for (int i = 0; i < 8; i++) { t0 += sh[0][i]; t1 += sh[1][i]; t2 += sh[2][i]; }
        sm0 = t0 / (float)NPTS;
        sm1 = t1 / (float)NPTS;
        sm2 = t2 / (float)NPTS;
        g_mean[b*3+0] = sm0;
        g_mean[b*3+1] = sm1;
        g_mean[b*3+2] = sm2;
    }
    __syncthreads();
    float m0 = sm0, m1 = sm1, m2 = sm2;
    float mx = 0.f;
    for (int n = tid; n < NPTS; n += 256) {
        float dx = cb[n] - m0, dy = cb[NPTS+n] - m1, dz = cb[2*NPTS+n] - m2;
        float sq = dx*dx + dy*dy + dz*dz;
        mx = fmaxf(mx, sq);
    }
    for (int o = 16; o; o >>= 1) mx = fmaxf(mx, __shfl_xor_sync(0xffffffffu, mx, o));
    __shared__ float shm[8];
    if ((tid & 31) == 0) shm[w] = mx;
    __syncthreads();
    if (tid == 0) {
        float t = 0.f;
        for (int i = 0; i < 8; i++) t = fmaxf(t, shm[i]);
        g_denom[b] = 2.0f * sqrtf(t);
    }
}

// ---------------------------------------------------------------------------
// 2. norm_coords + scatter-add (channel-last sums, v4 vector reductions)
// ---------------------------------------------------------------------------
__global__ void voxscatter_kernel(const float* __restrict__ coords,
                                  const float* __restrict__ features) {
    int t = blockIdx.x*blockDim.x + threadIdx.x;
    int b = t >> 15, n = t & (NPTS-1);
    float den = g_denom[b];
    int vi[3];
#pragma unroll
    for (int d = 0; d < 3; d++) {
        float c = coords[((size_t)b*3 + d)*NPTS + n];
        float v = (c - g_mean[b*3+d]) / den + 0.5f;
        v *= (float)RES;
        v = fminf(fmaxf(v, 0.f), (float)(RES-1));
        g_nc[((size_t)b*3 + d)*NPTS + n] = v;
        vi[d] = (int)rintf(v);
    }
    int vox = vi[0]*RES*RES + vi[1]*RES + vi[2];
    atomicAdd(&g_cnt[b*RCUBE + vox], 1.f);
    size_t fb = (size_t)b*CH*NPTS + n;
    size_t sb = ((size_t)b*RCUBE + vox)*64;
#pragma unroll 4
    for (int c = 0; c < CH; c += 4) {
        float v0 = features[fb + (size_t)(c+0)*NPTS];
        float v1 = features[fb + (size_t)(c+1)*NPTS];
        float v2 = features[fb + (size_t)(c+2)*NPTS];
        float v3 = features[fb + (size_t)(c+3)*NPTS];
        red_add_v4(&g_sums[sb + c], v0, v1, v2, v3);
    }
}

// ---------------------------------------------------------------------------
// 3. FUSED: average + fp16 convert (conv1 input prep), pure streaming
// ---------------------------------------------------------------------------
__global__ void avg_aprep_kernel() {
    int i = blockIdx.x*256 + threadIdx.x;
    int bv = i >> 4;
    float cv = fmaxf(g_cnt[bv], 1.f);
    float4 v = ((const float4*)g_sums)[i];
    ((__half2*)g_ahi)[i*2    ] = __halves2half2(__float2half_rn(v.x / cv),
                                                __float2half_rn(v.y / cv));
    ((__half2*)g_ahi)[i*2 + 1] = __halves2half2(__float2half_rn(v.z / cv),
                                                __float2half_rn(v.w / cv));
}

// ---------------------------------------------------------------------------
// 4. FUSED: instnorm-apply(+leaky) + channel-last fp16 convert (conv2 input prep)
// ---------------------------------------------------------------------------
__global__ void in_aprep_kernel(const float* __restrict__ ss, const float* __restrict__ sq) {
    __shared__ float t[32][33];
    int b = blockIdx.z, ct = blockIdx.y, vt = blockIdx.x;
    int tx = threadIdx.x & 31, ty = threadIdx.x >> 5;
    const float* s = g_tmp + ((size_t)b*CH + ct*32)*RCUBE + vt*32;
#pragma unroll
    for (int k = 0; k < 32; k += 8) {
        int c = ct*32 + ty + k;
        float m   = ss[b*CH + c] / (float)RCUBE;
        float var = fmaxf(sq[b*CH + c] / (float)RCUBE - m*m, 0.f);
        float rs  = rsqrtf(var + NORM_EPS);
        float v = (s[(size_t)(ty+k)*RCUBE + tx] - m) * rs;
        t[ty+k][tx] = (v >= 0.f) ? v : LEAK * v;
    }
    __syncthreads();
#pragma unroll
    for (int k = 0; k < 32; k += 8) {
        size_t di = ((size_t)b*RCUBE + vt*32 + ty + k)*CH + ct*32 + tx;
        g_ahi[di] = __float2half_rn(t[tx][ty+k]);
    }
}

// ---------------------------------------------------------------------------
// 5. FUSED: instnorm-apply(+leaky) -> out_vf [b][c][vox] AND g_vfth [b][vox][c] (fp16)
// ---------------------------------------------------------------------------
__global__ void in_dual_kernel(const float* __restrict__ ss, const float* __restrict__ sq,
                               float* __restrict__ out_vf) {
    __shared__ float t[32][33];
    int b = blockIdx.z, ct = blockIdx.y, vt = blockIdx.x;
    int tx = threadIdx.x & 31, ty = threadIdx.x >> 5;
    const float* s = g_tmp + ((size_t)b*CH + ct*32)*RCUBE + vt*32;
    float* o = out_vf + ((size_t)b*CH + ct*32)*RCUBE + vt*32;
#pragma unroll
    for (int k = 0; k < 32; k += 8) {
        int c = ct*32 + ty + k;
        float m   = ss[b*CH + c] / (float)RCUBE;
        float var = fmaxf(sq[b*CH + c] / (float)RCUBE - m*m, 0.f);
        float rs  = rsqrtf(var + NORM_EPS);
        float v = (s[(size_t)(ty+k)*RCUBE + tx] - m) * rs;
        v = (v >= 0.f) ? v : LEAK * v;
        o[(size_t)(ty+k)*RCUBE + tx] = v;
        t[ty+k][tx] = v;
    }
    __syncthreads();
#pragma unroll
    for (int k = 0; k < 32; k += 8) {
        size_t di = ((size_t)b*RCUBE + vt*32 + ty + k)*CH + ct*32 + tx;
        g_vfth[di] = __float2half_rn(t[tx][ty+k]);
    }
}

// ---------------------------------------------------------------------------
// 6a. weight prep: both conv weights in one launch
// ---------------------------------------------------------------------------
__global__ void wprep_kernel(const float* __restrict__ W1, const float* __restrict__ W2) {
    int i = blockIdx.x*256 + threadIdx.x;        // over 2*110592
    if (i >= 2*27*64*64) return;
    int which = i >= 27*64*64;
    int j = which ? i - 27*64*64 : i;
    int ci = j & 63;
    int rest = j >> 6;
    int co = rest & 63, off = rest >> 6;
    const float* W = which ? W2 : W1;
    __half v = __float2half_rn(W[((size_t)co*64 + ci)*27 + off]);
    if (which) g_w2h[j] = v;
    else       g_w1h[j] = v;
}

// ---------------------------------------------------------------------------
// 6b. Conv3d 3x3x3, single-pass fp16 mma, cp.async double-buffered (R14 best).
// ---------------------------------------------------------------------------
#define SA_BYTES (3*18*34*16*2)   // 58752
#define SW_BYTES (27*64*16*2)     // 55296
#define CONV_SMEM (2*SA_BYTES + 2*SW_BYTES)   // 228,096 bytes

__device__ __forceinline__ void conv_load_chunk(
    uint32_t sA_u32, uint32_t sW_u32, const __half* __restrict__ Whi,
    int b, int d, int h0, int ci0, int tid) {
    for (int u = tid; u < 2*3*18*34; u += 256) {
        int halfsel = u & 1, pos = u >> 1;
        int dd = pos / 612;
        int r  = pos - dd*612;
        int hy = r / 34;
        int ww = r - hy*34;
        int gd = d - 1 + dd, gh = h0 - 1 + hy, gw = ww - 1;
        bool inb = (unsigned)gd < 32u && (unsigned)gh < 32u && (unsigned)gw < 32u;
        size_t gi = inb ? ((size_t)b*RCUBE + gd*1024 + gh*32 + gw)*64 + ci0 + halfsel*8
                        : 0;
        int sz = inb ? 16 : 0;
        CP_ASYNC16(sA_u32 + u*16, g_ahi + gi, sz);
    }
    for (int u = tid; u < 2*27*64; u += 256) {
        int halfsel = u & 1, row = u >> 1;
        CP_ASYNC16(sW_u32 + u*16, Whi + (size_t)row*64 + ci0 + halfsel*8, 16);
    }
}

__global__ __launch_bounds__(256, 1)
void conv_mma_kernel(const __half* __restrict__ Whi,
                     const float* __restrict__ bias,
                     float* __restrict__ out,
                     float* __restrict__ ss, float* __restrict__ sq) {
    extern __shared__ __align__(16) char smem_raw[];
    char* pA[2] = { smem_raw, smem_raw + SA_BYTES };
    char* pW[2] = { smem_raw + 2*SA_BYTES, smem_raw + 2*SA_BYTES + SW_BYTES };
    uint32_t uA[2] = { smem_u32(pA[0]), smem_u32(pA[1]) };
    uint32_t uW[2] = { smem_u32(pW[0]), smem_u32(pW[1]) };

    int bid = blockIdx.x;
    int hh = bid & 1, d = (bid >> 1) & 31, b = bid >> 6;
    int h0 = hh * 16;
    int tid = threadIdx.x;
    int warp = tid >> 5, lane = tid & 31;
    int g = lane >> 2, tg = lane & 3;

    float acc[4][8][4];
#pragma unroll
    for (int t = 0; t < 4; t++)
#pragma unroll
        for (int n = 0; n < 8; n++)
#pragma unroll
            for (int e = 0; e < 4; e++) acc[t][n][e] = 0.f;

    int abase[4];
#pragma unroll
    for (int t = 0; t < 4; t++) {
        int h_loc = warp*2 + (t >> 1);
        int wb = (t & 1)*16;
        abase[t] = (h_loc*34 + wb + g)*32 + tg*4;
    }
    int bthread = g*32 + tg*4;

    conv_load_chunk(uA[0], uW[0], Whi, b, d, h0, 0, tid);
    CP_COMMIT();
    CP_WAIT0();
    __syncthreads();

#pragma unroll 1
    for (int cq = 0; cq < 4; cq++) {
        int buf = cq & 1;
        if (cq < 3) {
            conv_load_chunk(uA[buf^1], uW[buf^1], Whi, b, d, h0, (cq+1)*16, tid);
            CP_COMMIT();
        }

        const char* sAh = pA[buf];
        const char* sWh = pW[buf];
        int dd = 0, dh = 0, dw = 0;
#pragma unroll 1
        for (int off = 0; off < 27; ++off) {
            int rowoff = ((dd*18 + dh)*34 + dw)*32;
            uint32_t ah[4][4];
#pragma unroll
            for (int t = 0; t < 4; ++t) {
                const char* pa = sAh + rowoff + abase[t];
                ah[t][0] = *(const uint32_t*)(pa);
                ah[t][2] = *(const uint32_t*)(pa + 16);
                ah[t][1] = *(const uint32_t*)(pa + 256);
                ah[t][3] = *(const uint32_t*)(pa + 272);
            }
            int bo = off*2048 + bthread;
#pragma unroll
            for (int n8 = 0; n8 < 8; ++n8) {
                const char* pbh = sWh + bo + n8*256;
                uint32_t bh0 = *(const uint32_t*)(pbh);
                uint32_t bh1 = *(const uint32_t*)(pbh + 16);
#pragma unroll
                for (int t = 0; t < 4; ++t)
                    mma_fp16(acc[t][n8], ah[t], bh0, bh1);
            }
            if (++dw == 3) { dw = 0; if (++dh == 3) { dh = 0; ++dd; } }
        }

        CP_WAIT0();
        __syncthreads();
    }

#pragma unroll
    for (int n8 = 0; n8 < 8; ++n8) {
#pragma unroll
        for (int par = 0; par < 2; ++par) {
            int co = n8*8 + 2*tg + par;
            float bb = __ldg(&bias[co]);
            float s = 0.f, q = 0.f;
            size_t obase = ((size_t)b*CH + co)*RCUBE + d*1024;
#pragma unroll
            for (int t = 0; t < 4; ++t) {
                int h_loc = warp*2 + (t >> 1);
                int wb = (t & 1)*16;
#pragma unroll
                for (int rh = 0; rh < 2; ++rh) {
                    float v = acc[t][n8][rh*2 + par] + bb;
                    out[obase + (h0 + h_loc)*32 + wb + g + rh*8] = v;
                    s += v;
                    q = fmaf(v, v, q);
                }
            }
            s += __shfl_xor_sync(0xffffffffu, s, 4);
            q += __shfl_xor_sync(0xffffffffu, q, 4);
            s += __shfl_xor_sync(0xffffffffu, s, 8);
            q += __shfl_xor_sync(0xffffffffu, q, 8);
            s += __shfl_xor_sync(0xffffffffu, s, 16);
            q += __shfl_xor_sync(0xffffffffu, q, 16);
            if (g == 0) {
                atomicAdd(&ss[b*CH + co], s);
                atomicAdd(&sq[b*CH + co], q);
            }
        }
    }
}

// ---------------------------------------------------------------------------
// 7. point branch GEMM, fp16 output + fused IN-stat accumulation
// ---------------------------------------------------------------------------
__global__ void pointmlp_kernel(const float* __restrict__ features,
                                const float* __restrict__ pw,
                                const float* __restrict__ pb) {
    __shared__ float sw[64*64];
    __shared__ float sb[64];
    int tid = threadIdx.x;
    for (int i = tid; i < 4096; i += 256) sw[i] = pw[i];
    if (tid < 64) sb[tid] = pb[tid];
    __syncthreads();
    int blk = blockIdx.x;
    int b = blk >> 7;
    int n = (blk & 127)*256 + tid;
    float acc[64];
#pragma unroll
    for (int o = 0; o < 64; o++) acc[o] = 0.f;
    const float* f = features + (size_t)b*CH*NPTS + n;
    for (int c = 0; c < 64; c++) {
        float v = f[(size_t)c*NPTS];
#pragma unroll
        for (int o = 0; o < 64; o++) acc[o] = fmaf(sw[o*64 + c], v, acc[o]);
    }
    __half* p = g_p16 + (size_t)b*CH*NPTS + n;
#pragma unroll
    for (int o = 0; o < 64; o++) {
        float v = acc[o] + sb[o];
        p[(size_t)o*NPTS] = __float2half_rn(v);
        float s = v, q = v*v;
        for (int off = 16; off; off >>= 1) {
            s += __shfl_xor_sync(0xffffffffu, s, off);
            q += __shfl_xor_sync(0xffffffffu, q, off);
        }
        if ((tid & 31) == 0) {
            atomicAdd(&g_psts[b*CH + o], s);
            atomicAdd(&g_pstq[b*CH + o], q);
        }
    }
}

// ---------------------------------------------------------------------------
// 8. FUSED final: trilinear devoxelize (fp16 gather) + point-norm + add -> out
// ---------------------------------------------------------------------------
__global__ void final_kernel(float* __restrict__ outf) {
    __shared__ float t[32][65];
    int blk = blockIdx.x;
    int b = blk >> 10;
    int n0 = (blk & 1023)*32;
    int tid = threadIdx.x;
    int warp = tid >> 5, lane = tid & 31;

#pragma unroll
    for (int j = 0; j < 4; j++) {
        int nl = warp*4 + j;
        int n = n0 + nl;
        float nx = g_nc[((size_t)b*3 + 0)*NPTS + n];
        float ny = g_nc[((size_t)b*3 + 1)*NPTS + n];
        float nz = g_nc[((size_t)b*3 + 2)*NPTS + n];
        int lx = (int)floorf(nx), ly = (int)floorf(ny), lz = (int)floorf(nz);
        float fx = nx - (float)lx, fy = ny - (float)ly, fz = nz - (float)lz;
        int hx = min(lx+1, 31), hy = min(ly+1, 31), hz = min(lz+1, 31);
        const __half* base = g_vfth + (size_t)b*RCUBE*CH;
        float a0 = 0.f, a1 = 0.f;
#pragma unroll
        for (int k = 0; k < 8; k++) {
            int dx = k >> 2, dy = (k >> 1) & 1, dz = k & 1;
            int ix = dx ? hx : lx, iy = dy ? hy : ly, iz = dz ? hz : lz;
            float wgt = (dx ? fx : 1.f-fx) * (dy ? fy : 1.f-fy) * (dz ? fz : 1.f-fz);
            const __half2* p = (const __half2*)(base + (size_t)(ix*1024 + iy*32 + iz)*CH);
            float2 f2 = __half22float2(p[lane]);
            a0 = fmaf(wgt, f2.x, a0);
            a1 = fmaf(wgt, f2.y, a1);
        }
        t[nl][2*lane]     = a0;
        t[nl][2*lane + 1] = a1;
    }
    __syncthreads();

    size_t ob = (size_t)b*CH*NPTS + n0;
    for (int i = tid; i < 2048; i += 256) {
        int nl = i & 31, c = i >> 5;
        float m   = g_psts[b*CH + c] / (float)NPTS;
        float var = fmaxf(g_pstq[b*CH + c] / (float)NPTS - m*m, 0.f);
        float rs  = rsqrtf(var + NORM_EPS);
        size_t o = ob + (size_t)c*NPTS + nl;
        float v = (__half2float(g_p16[o]) - m) * rs;
        v = (v >= 0.f) ? v : LEAK * v;
        outf[o] = t[nl][c] + v;
    }
}

// ---------------------------------------------------------------------------
// launch — fork/join: point branch + weight prep on a side stream
// ---------------------------------------------------------------------------
extern "C" void kernel_launch(void* const* d_in, const int* in_sizes, int n_in,
                              void* d_out, int out_size) {
    const float* features = (const float*)d_in[0];
    const float* coords   = (const float*)d_in[1];
    const float* c1w      = (const float*)d_in[2];
    const float* c1b      = (const float*)d_in[3];
    const float* c2w      = (const float*)d_in[4];
    const float* c2b      = (const float*)d_in[5];
    const float* pw       = (const float*)d_in[6];
    const float* pb       = (const float*)d_in[7];
    float* out = (float*)d_out;
    float* out_fused  = out + OFF_FUSED;
    float* out_coords = out + OFF_COORDS;
    float* out_vf     = out + OFF_VF;

    float *p_tmp, *p_sums, *p_cnt;
    float *p_s1s, *p_s1q, *p_s2s, *p_s2q;
    __half *p_w1h, *p_w2h;
    cudaGetSymbolAddress((void**)&p_tmp,  g_tmp);
    cudaGetSymbolAddress((void**)&p_sums, g_sums);
    cudaGetSymbolAddress((void**)&p_cnt,  g_cnt);
    cudaGetSymbolAddress((void**)&p_s1s,  g_st1s);
    cudaGetSymbolAddress((void**)&p_s1q,  g_st1q);
    cudaGetSymbolAddress((void**)&p_s2s,  g_st2s);
    cudaGetSymbolAddress((void**)&p_s2q,  g_st2q);
    cudaGetSymbolAddress((void**)&p_w1h,  g_w1h);
    cudaGetSymbolAddress((void**)&p_w2h,  g_w2h);

    cudaFuncSetAttribute(conv_mma_kernel,
                         cudaFuncAttributeMaxDynamicSharedMemorySize, CONV_SMEM);

    // fork/join resources (created per call; tiny host-side objects)
    cudaStream_t s2;
    cudaStreamCreateWithFlags(&s2, cudaStreamNonBlocking);
    cudaEvent_t evFork, evJoin;
    cudaEventCreateWithFlags(&evFork, cudaEventDisableTiming);
    cudaEventCreateWithFlags(&evJoin, cudaEventDisableTiming);

    // stats must be zeroed before BOTH branches (pointmlp accumulates g_psts)
    zero_stats_kernel<<<2, 256>>>();
    cudaEventRecord(evFork, 0);
    cudaStreamWaitEvent(s2, evFork, 0);

    // ---- side stream: point branch + weight prep + coords copy ----
    wprep_kernel<<<(2*27*64*64 + 255)/256, 256, 0, s2>>>(c1w, c2w);
    pointmlp_kernel<<<BATCH*128, 256, 0, s2>>>(features, pw, pb);
    cudaMemcpyAsync(out_coords, coords, (size_t)BATCH*3*NPTS*sizeof(float),
                    cudaMemcpyDeviceToDevice, s2);
    cudaEventRecord(evJoin, s2);

    // ---- main stream: voxel chain front-end ----
    cudaMemsetAsync(p_sums, 0, (size_t)GRID_ELEMS*sizeof(float));
    cudaMemsetAsync(p_cnt,  0, (size_t)BATCH*RCUBE*sizeof(float));
    meannorm_kernel<<<BATCH, 256>>>(coords);
    voxscatter_kernel<<<BATCH*NPTS/256, 256>>>(coords, features);
    avg_aprep_kernel<<<GRID_ELEMS/4/256, 256>>>();

    // join: conv1 needs weights; final needs pointmlp (already covered)
    cudaStreamWaitEvent(0, evJoin, 0);

    conv_mma_kernel<<<BATCH*32*2, 256, CONV_SMEM>>>(p_w1h, c1b, p_tmp, p_s1s, p_s1q);
    in_aprep_kernel<<<dim3(1024, 2, BATCH), 256>>>(p_s1s, p_s1q);
    conv_mma_kernel<<<BATCH*32*2, 256, CONV_SMEM>>>(p_w2h, c2b, p_tmp, p_s2s, p_s2q);
    in_dual_kernel<<<dim3(1024, 2, BATCH), 256>>>(p_s2s, p_s2q, out_vf);

    final_kernel<<<BATCH*1024, 256>>>(out_fused);
}